// round 1
// baseline (speedup 1.0000x reference)
#include <cuda_runtime.h>
#include <math.h>

// ---------------- problem constants ----------------
#define SS    2048
#define NN_   10
#define DD    172
#define EDGE  172
#define TDD   100
#define EE    272      // query/embed dim
#define KD_   444      // per-neighbor key dim
#define KDT   4440     // flattened key dim
#define HD    136      // head dim (E/H)
#define M0    20480    // prop0 rows (S*N)
#define MT    22528    // total combined rows (M0 + S)
#define NKV   544      // kp|vp combined

// ---------------- scratch (single static device array) ----------------
static const size_t SZ_PACKED = (size_t)MT * KDT;       // 100,024,320
static const size_t SZ_QIN    = (size_t)MT * EE;        //   6,127,616
static const size_t SZ_KPVP   = (size_t)MT * NKV;       //  12,255,232
static const size_t SZ_QP     = (size_t)MT * EE;
static const size_t SZ_O      = (size_t)MT * EE;
static const size_t SZ_A      = (size_t)MT * EE;
static const size_t SZ_FFNIN  = (size_t)MT * KD_;       //  10,002,432
static const size_t SZ_H      = (size_t)MT * DD;        //   3,874,816
static const size_t SZ_SC     = (size_t)2 * SS * SS;    //   8,388,608
static const size_t SZ_WKV    = (size_t)NKV * KDT;      //   2,415,360
static const size_t SZ_BKV    = 1024;

static const size_t OFF_PACKED = 0;
static const size_t OFF_QIN    = OFF_PACKED + SZ_PACKED;
static const size_t OFF_KPVP   = OFF_QIN    + SZ_QIN;
static const size_t OFF_QP     = OFF_KPVP   + SZ_KPVP;
static const size_t OFF_O      = OFF_QP     + SZ_QP;
static const size_t OFF_A      = OFF_O      + SZ_O;
static const size_t OFF_FFNIN  = OFF_A      + SZ_A;
static const size_t OFF_H      = OFF_FFNIN  + SZ_FFNIN;
static const size_t OFF_SC     = OFF_H      + SZ_H;
static const size_t OFF_WKV    = OFF_SC     + SZ_SC;
static const size_t OFF_BKV    = OFF_WKV    + SZ_WKV;
static const size_t SZ_TOTAL   = OFF_BKV    + SZ_BKV;   // ~161.5M floats (~646 MB)

__device__ float g_scratch[SZ_TOTAL];

// ---------------- pack kernels ----------------

// packed[r][j*444+c] : r<M0 -> (emb0|edge0|td0)[r, j, c] ; else (emb1|edge1|td1)[r-M0, j, c]
__global__ void pack_big_kernel(const float* __restrict__ emb0, const float* __restrict__ edge0,
                                const float* __restrict__ td0,  const float* __restrict__ emb1,
                                const float* __restrict__ edge1,const float* __restrict__ td1,
                                float* __restrict__ packed)
{
    int c = blockIdx.x * blockDim.x + threadIdx.x;
    int r = blockIdx.y;
    if (c >= KDT) return;
    int j  = c / KD_;
    int cc = c - j * KD_;
    const float *pe, *pg, *pt; int i;
    if (r < M0) { pe = emb0; pg = edge0; pt = td0; i = r; }
    else        { pe = emb1; pg = edge1; pt = td1; i = r - M0; }
    float v;
    if (cc < DD)           v = pe[(size_t)(i * NN_ + j) * DD   + cc];
    else if (cc < DD+EDGE) v = pg[(size_t)(i * NN_ + j) * EDGE + (cc - DD)];
    else                   v = pt[(size_t)(i * NN_ + j) * TDD  + (cc - DD - EDGE)];
    packed[(size_t)r * KDT + c] = v;
}

// qin[r] = r<M0 ? [emb1_flat[r] | td1_flat[r]] : [emb2[r-M0] | zeros]
__global__ void pack_qin_kernel(const float* __restrict__ emb1, const float* __restrict__ td1,
                                const float* __restrict__ emb2, float* __restrict__ qin)
{
    size_t idx = (size_t)blockIdx.x * blockDim.x + threadIdx.x;
    if (idx >= (size_t)MT * EE) return;
    int r = (int)(idx / EE);
    int c = (int)(idx - (size_t)r * EE);
    float v;
    if (r < M0) v = (c < DD) ? emb1[(size_t)r * DD + c] : td1[(size_t)r * TDD + (c - DD)];
    else {
        int t = r - M0;
        v = (c < DD) ? emb2[(size_t)t * DD + c] : 0.f;
    }
    qin[idx] = v;
}

__global__ void pack_w_kernel(const float* __restrict__ Wk, const float* __restrict__ Wv,
                              const float* __restrict__ bk, const float* __restrict__ bv,
                              float* __restrict__ Wkv, float* __restrict__ bkv)
{
    size_t idx = (size_t)blockIdx.x * blockDim.x + threadIdx.x;
    if (idx < (size_t)NKV * KDT) {
        int f = (int)(idx / KDT);
        int k = (int)(idx - (size_t)f * KDT);
        Wkv[idx] = (f < EE) ? Wk[(size_t)f * KDT + k] : Wv[(size_t)(f - EE) * KDT + k];
    }
    if (idx < NKV) bkv[idx] = (idx < EE) ? bk[idx] : bv[idx - EE];
}

// ffnin[r] = [a[r] (272) | embrow (172)]
__global__ void pack_ffnin_kernel(const float* __restrict__ a, const float* __restrict__ emb1,
                                  const float* __restrict__ emb2, float* __restrict__ ffnin)
{
    size_t idx = (size_t)blockIdx.x * blockDim.x + threadIdx.x;
    if (idx >= (size_t)MT * KD_) return;
    int r = (int)(idx / KD_);
    int c = (int)(idx - (size_t)r * KD_);
    float v;
    if (c < EE) v = a[(size_t)r * EE + c];
    else {
        int cc = c - EE;
        v = (r < M0) ? emb1[(size_t)r * DD + cc] : emb2[(size_t)(r - M0) * DD + cc];
    }
    ffnin[idx] = v;
}

// ---------------- generic tiled fp32 GEMM ----------------
// C[m,n] = alpha*(sum_k A[m,k]*B(k,n)) + alpha*bias[n]   (then optional relu)
// BT=true : B is (N,K) row-major (C = A * B^T)
// BT=false: B is (K,N) row-major (C = A * B)
#define BM 128
#define BN 64
#define BKK 8

template<bool BT>
__global__ void __launch_bounds__(256)
gemm_kernel(const float* __restrict__ A, const float* __restrict__ B, float* __restrict__ C,
            int M, int N, int K, int lda, int ldb, int ldc,
            const float* __restrict__ bias, float alpha, int relu)
{
    __shared__ float As[BKK][BM + 4];
    __shared__ float Bs[BKK][BN + 4];
    int tid = threadIdx.x;
    int m0 = blockIdx.y * BM;
    int n0 = blockIdx.x * BN;
    int tx = tid & 15;        // 16 -> 64 cols (4 each)
    int ty = tid >> 4;        // 16 -> 128 rows (8 each)

    float acc[8][4];
#pragma unroll
    for (int i = 0; i < 8; i++)
#pragma unroll
        for (int j = 0; j < 4; j++) acc[i][j] = 0.f;

    int arow = tid >> 1;
    int acol = (tid & 1) * 4;

    for (int k0 = 0; k0 < K; k0 += BKK) {
        // --- load A tile (128 x 8), store transposed ---
        float4 av = make_float4(0.f, 0.f, 0.f, 0.f);
        int ka = k0 + acol;
        if (m0 + arow < M && ka < K)
            av = *(const float4*)(A + (size_t)(m0 + arow) * lda + ka);
        As[acol + 0][arow] = av.x;
        As[acol + 1][arow] = av.y;
        As[acol + 2][arow] = av.z;
        As[acol + 3][arow] = av.w;
        // --- load B tile ---
        if (tid < 128) {
            if (BT) {
                int brow = tid >> 1, bcol = (tid & 1) * 4;
                float4 bv = make_float4(0.f, 0.f, 0.f, 0.f);
                int kb = k0 + bcol;
                if (n0 + brow < N && kb < K)
                    bv = *(const float4*)(B + (size_t)(n0 + brow) * ldb + kb);
                Bs[bcol + 0][brow] = bv.x;
                Bs[bcol + 1][brow] = bv.y;
                Bs[bcol + 2][brow] = bv.z;
                Bs[bcol + 3][brow] = bv.w;
            } else {
                int krow = tid >> 4, nc = (tid & 15) * 4;
                float4 bv = make_float4(0.f, 0.f, 0.f, 0.f);
                if (k0 + krow < K && n0 + nc < N)
                    bv = *(const float4*)(B + (size_t)(k0 + krow) * ldb + n0 + nc);
                *(float4*)&Bs[krow][nc] = bv;
            }
        }
        __syncthreads();
#pragma unroll
        for (int kk = 0; kk < BKK; kk++) {
            float a[8], b[4];
            *(float4*)&a[0] = *(const float4*)&As[kk][ty * 8];
            *(float4*)&a[4] = *(const float4*)&As[kk][ty * 8 + 4];
            *(float4*)&b[0] = *(const float4*)&Bs[kk][tx * 4];
#pragma unroll
            for (int i = 0; i < 8; i++)
#pragma unroll
                for (int j = 0; j < 4; j++)
                    acc[i][j] += a[i] * b[j];
        }
        __syncthreads();
    }
#pragma unroll
    for (int i = 0; i < 8; i++) {
        int m = m0 + ty * 8 + i;
        if (m >= M) continue;
#pragma unroll
        for (int j = 0; j < 4; j++) {
            int n = n0 + tx * 4 + j;
            if (n >= N) continue;
            float v = acc[i][j] * alpha;
            if (bias) v += alpha * bias[n];
            if (relu) v = fmaxf(v, 0.f);
            C[(size_t)m * ldc + n] = v;
        }
    }
}

// ---------------- prop0 attention: one block per source node s ----------------
__global__ void __launch_bounds__(256)
attn0_kernel(const float* __restrict__ qp, const float* __restrict__ kpvp, float* __restrict__ o)
{
    int s = blockIdx.x;
    __shared__ float qs[NN_][EE + 1];
    __shared__ float ks[NN_][EE + 1];
    __shared__ float vs[NN_][EE + 1];
    __shared__ float p[2][NN_][NN_];
    int tid = threadIdx.x;

    for (int idx = tid; idx < NN_ * EE; idx += 256) {
        int n = idx / EE, e = idx - n * EE;
        size_t row = (size_t)(s * NN_ + n);
        qs[n][e] = qp[row * EE + e];
        ks[n][e] = kpvp[row * NKV + e];
        vs[n][e] = kpvp[row * NKV + EE + e];
    }
    __syncthreads();

    if (tid < 200) {
        int h = tid / 100, q = (tid / 10) % 10, k = tid % 10;
        float acc = 0.f;
        const float* qr = &qs[q][h * HD];
        const float* kr = &ks[k][h * HD];
#pragma unroll 8
        for (int d = 0; d < HD; d++) acc += qr[d] * kr[d];
        p[h][q][k] = acc;
    }
    __syncthreads();

    if (tid < 20) {
        int h = tid / 10, q = tid % 10;
        float mx = -1e30f;
#pragma unroll
        for (int k = 0; k < NN_; k++) mx = fmaxf(mx, p[h][q][k]);
        float sum = 0.f;
#pragma unroll
        for (int k = 0; k < NN_; k++) { float e = expf(p[h][q][k] - mx); p[h][q][k] = e; sum += e; }
        float inv = 1.f / sum;
#pragma unroll
        for (int k = 0; k < NN_; k++) p[h][q][k] *= inv;
    }
    __syncthreads();

    for (int idx = tid; idx < NN_ * EE; idx += 256) {
        int q = idx / EE, e = idx - q * EE;
        int h = e / HD;
        float acc = 0.f;
#pragma unroll
        for (int k = 0; k < NN_; k++) acc += p[h][q][k] * vs[k][e];
        o[(size_t)(s * NN_ + q) * EE + e] = acc;
    }
}

// ---------------- row softmax over 2048 cols ----------------
__global__ void __launch_bounds__(256)
softmax2048_kernel(float* __restrict__ Smat)
{
    int row = blockIdx.x;               // 2*2048 rows
    float* r = Smat + (size_t)row * SS;
    int tid = threadIdx.x;
    __shared__ float red[256];

    float v[8];
    float mx = -1e30f;
#pragma unroll
    for (int i = 0; i < 8; i++) { v[i] = r[tid + 256 * i]; mx = fmaxf(mx, v[i]); }
    red[tid] = mx; __syncthreads();
    for (int sft = 128; sft > 0; sft >>= 1) {
        if (tid < sft) red[tid] = fmaxf(red[tid], red[tid + sft]);
        __syncthreads();
    }
    mx = red[0]; __syncthreads();

    float sum = 0.f;
#pragma unroll
    for (int i = 0; i < 8; i++) { v[i] = expf(v[i] - mx); sum += v[i]; }
    red[tid] = sum; __syncthreads();
    for (int sft = 128; sft > 0; sft >>= 1) {
        if (tid < sft) red[tid] += red[tid + sft];
        __syncthreads();
    }
    float inv = 1.f / red[0];
#pragma unroll
    for (int i = 0; i < 8; i++) r[tid + 256 * i] = v[i] * inv;
}

// ---------------- host launcher ----------------
static inline void gemm_nt(const float* A, const float* B, float* C, int M, int N, int K,
                           int lda, int ldb, int ldc, const float* bias, float alpha, int relu)
{
    dim3 g((N + BN - 1) / BN, (M + BM - 1) / BM);
    gemm_kernel<true><<<g, 256>>>(A, B, C, M, N, K, lda, ldb, ldc, bias, alpha, relu);
}
static inline void gemm_nn(const float* A, const float* B, float* C, int M, int N, int K,
                           int lda, int ldb, int ldc, const float* bias, float alpha, int relu)
{
    dim3 g((N + BN - 1) / BN, (M + BM - 1) / BM);
    gemm_kernel<false><<<g, 256>>>(A, B, C, M, N, K, lda, ldb, ldc, bias, alpha, relu);
}

extern "C" void kernel_launch(void* const* d_in, const int* in_sizes, int n_in,
                              void* d_out, int out_size)
{
    const float* emb0  = (const float*)d_in[0];
    const float* edge0 = (const float*)d_in[1];
    const float* td0   = (const float*)d_in[2];
    const float* emb1  = (const float*)d_in[3];
    const float* edge1 = (const float*)d_in[4];
    const float* td1   = (const float*)d_in[5];
    const float* emb2  = (const float*)d_in[6];
    const float* Wq = (const float*)d_in[7];
    const float* bq = (const float*)d_in[8];
    const float* Wk = (const float*)d_in[9];
    const float* bk = (const float*)d_in[10];
    const float* Wv = (const float*)d_in[11];
    const float* bv = (const float*)d_in[12];
    const float* Wo = (const float*)d_in[13];
    const float* bo = (const float*)d_in[14];
    const float* W1 = (const float*)d_in[15];
    const float* b1 = (const float*)d_in[16];
    const float* W2 = (const float*)d_in[17];
    const float* b2 = (const float*)d_in[18];
    float* out = (float*)d_out;

    float* base = nullptr;
    cudaGetSymbolAddress((void**)&base, g_scratch);
    float* packed = base + OFF_PACKED;
    float* qin    = base + OFF_QIN;
    float* kpvp   = base + OFF_KPVP;
    float* qp     = base + OFF_QP;
    float* o      = base + OFF_O;
    float* a      = base + OFF_A;
    float* ffnin  = base + OFF_FFNIN;
    float* h      = base + OFF_H;
    float* sc     = base + OFF_SC;
    float* Wkv    = base + OFF_WKV;
    float* bkv    = base + OFF_BKV;

    const float qscale = 1.f / sqrtf((float)HD);

    // --- packs ---
    {
        size_t n = (size_t)NKV * KDT;
        pack_w_kernel<<<(unsigned)((n + 255) / 256), 256>>>(Wk, Wv, bk, bv, Wkv, bkv);
    }
    pack_big_kernel<<<dim3((KDT + 255) / 256, MT), 256>>>(emb0, edge0, td0, emb1, edge1, td1, packed);
    {
        size_t n = (size_t)MT * EE;
        pack_qin_kernel<<<(unsigned)((n + 255) / 256), 256>>>(emb1, td1, emb2, qin);
    }

    // --- projections (combined prop0+prop1 rows) ---
    gemm_nt(packed, Wkv, kpvp, MT, NKV, KDT, KDT, KDT, NKV, bkv, 1.f, 0);     // kp|vp
    gemm_nt(qin, Wq, qp, MT, EE, EE, EE, EE, EE, bq, qscale, 0);              // qp (scaled)

    // --- prop0 attention (2048 tiny attentions) ---
    attn0_kernel<<<SS, 256>>>(qp, kpvp, o);

    // --- prop1 attention (full 2048x2048, 2 heads) ---
    for (int hh = 0; hh < 2; hh++) {
        gemm_nt(qp + (size_t)M0 * EE + hh * HD,
                kpvp + (size_t)M0 * NKV + hh * HD,
                sc + (size_t)hh * SS * SS,
                SS, SS, HD, EE, NKV, SS, nullptr, 1.f, 0);
    }
    softmax2048_kernel<<<2 * SS, 256>>>(sc);
    for (int hh = 0; hh < 2; hh++) {
        gemm_nn(sc + (size_t)hh * SS * SS,
                kpvp + (size_t)M0 * NKV + EE + hh * HD,
                o + (size_t)M0 * EE + hh * HD,
                SS, HD, SS, SS, NKV, EE, nullptr, 1.f, 0);
    }

    // --- output projection + FFN (combined rows) ---
    gemm_nt(o, Wo, a, MT, EE, EE, EE, EE, EE, bo, 1.f, 0);
    {
        size_t n = (size_t)MT * KD_;
        pack_ffnin_kernel<<<(unsigned)((n + 255) / 256), 256>>>(a, emb1, emb2, ffnin);
    }
    gemm_nt(ffnin, W1, h, MT, DD, KD_, KD_, KD_, DD, b1, 1.f, 1);             // relu
    gemm_nt(h, W2, out, MT, DD, DD, DD, DD, DD, b2, 1.f, 0);                  // r0 | r1 contiguous

    // --- passthrough outputs ---
    const size_t r_elems  = (size_t)MT * DD;           // 3,874,816  (r0 + r1)
    const size_t e_elems  = (size_t)M0 * EDGE;         // 3,522,560
    const size_t t_elems  = (size_t)M0 * TDD;          // 2,048,000
    cudaMemcpyAsync(out + r_elems, edge1, e_elems * sizeof(float), cudaMemcpyDeviceToDevice);
    cudaMemcpyAsync(out + r_elems + e_elems, td1, t_elems * sizeof(float), cudaMemcpyDeviceToDevice);
}

// round 9
// speedup vs baseline: 1.6713x; 1.6713x over previous
#include <cuda_runtime.h>
#include <cuda_bf16.h>
#include <math.h>
#include <stdint.h>

// ---------------- problem constants ----------------
#define SS    2048
#define NN_   10
#define DD    172
#define EDGE  172
#define TDD   100
#define EE    272      // query/embed dim
#define KD_   444      // per-neighbor key dim
#define KDT   4440     // flattened key dim
#define HD    136      // head dim (E/H)
#define M0    20480    // prop0 rows (S*N)
#define MT    22528    // total combined rows (M0 + S)
#define NKV   544      // kp|vp combined
#define K_PAD 4480     // KDT padded to multiple of 32

// ---------------- scratch ----------------
static const size_t SZ_QIN    = (size_t)MT * EE;
static const size_t SZ_KPVP   = (size_t)MT * NKV;
static const size_t SZ_QP     = (size_t)MT * EE;
static const size_t SZ_O      = (size_t)MT * EE;
static const size_t SZ_A      = (size_t)MT * EE;
static const size_t SZ_FFNIN  = (size_t)MT * KD_;
static const size_t SZ_H      = (size_t)MT * DD;
static const size_t SZ_SC     = (size_t)2 * SS * SS;
static const size_t SZ_BKV    = 1024;

static const size_t OFF_QIN    = 0;
static const size_t OFF_KPVP   = OFF_QIN    + SZ_QIN;
static const size_t OFF_QP     = OFF_KPVP   + SZ_KPVP;
static const size_t OFF_O      = OFF_QP     + SZ_QP;
static const size_t OFF_A      = OFF_O      + SZ_O;
static const size_t OFF_FFNIN  = OFF_A      + SZ_A;
static const size_t OFF_H      = OFF_FFNIN  + SZ_FFNIN;
static const size_t OFF_SC     = OFF_H      + SZ_H;
static const size_t OFF_BKV    = OFF_SC     + SZ_SC;
static const size_t SZ_TOTAL   = OFF_BKV    + SZ_BKV;

__device__ float g_scratch[SZ_TOTAL];
__device__ __nv_bfloat16 g_Ahi[(size_t)MT * K_PAD];
__device__ __nv_bfloat16 g_Alo[(size_t)MT * K_PAD];
__device__ __nv_bfloat16 g_Bhi[(size_t)NKV * K_PAD];
__device__ __nv_bfloat16 g_Blo[(size_t)NKV * K_PAD];

// ---------------- cp.async helpers (sm_80 base features, OK on sm_103) ----------------
__device__ __forceinline__ uint32_t smem_u32(const void* p) {
    uint32_t a;
    asm("{ .reg .u64 t; cvta.to.shared.u64 t, %1; cvt.u32.u64 %0, t; }" : "=r"(a) : "l"(p));
    return a;
}
#define CP_ASYNC16(dst, src, srcsize) \
    asm volatile("cp.async.cg.shared.global [%0], [%1], 16, %2;" \
                 :: "r"(dst), "l"(src), "r"(srcsize))
#define CP_COMMIT() asm volatile("cp.async.commit_group;")
#define CP_WAIT1()  asm volatile("cp.async.wait_group 1;")
#define CP_WAIT0()  asm volatile("cp.async.wait_group 0;")

__device__ __forceinline__ void mma_bf16(float c[4], uint32_t a0, uint32_t a1, uint32_t a2, uint32_t a3,
                                         uint32_t b0, uint32_t b1) {
    asm volatile(
        "mma.sync.aligned.m16n8k16.row.col.f32.bf16.bf16.f32 "
        "{%0,%1,%2,%3}, {%4,%5,%6,%7}, {%8,%9}, {%0,%1,%2,%3};"
        : "+f"(c[0]), "+f"(c[1]), "+f"(c[2]), "+f"(c[3])
        : "r"(a0), "r"(a1), "r"(a2), "r"(a3), "r"(b0), "r"(b1));
}

// ---------------- pack kernels (bf16 hi/lo) ----------------
__global__ void pack_big_bf16(const float* __restrict__ emb0, const float* __restrict__ edge0,
                              const float* __restrict__ td0,  const float* __restrict__ emb1,
                              const float* __restrict__ edge1,const float* __restrict__ td1,
                              __nv_bfloat16* __restrict__ Ahi, __nv_bfloat16* __restrict__ Alo)
{
    int c = blockIdx.x * blockDim.x + threadIdx.x;
    int r = blockIdx.y;
    if (c >= K_PAD) return;
    float v = 0.f;
    if (c < KDT) {
        int j  = c / KD_;
        int cc = c - j * KD_;
        const float *pe, *pg, *pt; int i;
        if (r < M0) { pe = emb0; pg = edge0; pt = td0; i = r; }
        else        { pe = emb1; pg = edge1; pt = td1; i = r - M0; }
        if (cc < DD)           v = pe[(size_t)(i * NN_ + j) * DD   + cc];
        else if (cc < DD+EDGE) v = pg[(size_t)(i * NN_ + j) * EDGE + (cc - DD)];
        else                   v = pt[(size_t)(i * NN_ + j) * TDD  + (cc - DD - EDGE)];
    }
    __nv_bfloat16 hi = __float2bfloat16(v);
    __nv_bfloat16 lo = __float2bfloat16(v - __bfloat162float(hi));
    size_t idx = (size_t)r * K_PAD + c;
    Ahi[idx] = hi;
    Alo[idx] = lo;
}

__global__ void pack_wkv_bf16(const float* __restrict__ Wk, const float* __restrict__ Wv,
                              const float* __restrict__ bk, const float* __restrict__ bv,
                              __nv_bfloat16* __restrict__ Bhi, __nv_bfloat16* __restrict__ Blo,
                              float* __restrict__ bkv)
{
    size_t idx = (size_t)blockIdx.x * blockDim.x + threadIdx.x;
    if (idx < (size_t)NKV * K_PAD) {
        int f = (int)(idx / K_PAD);
        int k = (int)(idx - (size_t)f * K_PAD);
        float v = 0.f;
        if (k < KDT)
            v = (f < EE) ? Wk[(size_t)f * KDT + k] : Wv[(size_t)(f - EE) * KDT + k];
        __nv_bfloat16 hi = __float2bfloat16(v);
        __nv_bfloat16 lo = __float2bfloat16(v - __bfloat162float(hi));
        Bhi[idx] = hi;
        Blo[idx] = lo;
    }
    if (idx < NKV) bkv[idx] = (idx < EE) ? bk[idx] : bv[idx - EE];
}

__global__ void pack_qin_kernel(const float* __restrict__ emb1, const float* __restrict__ td1,
                                const float* __restrict__ emb2, float* __restrict__ qin)
{
    size_t idx = (size_t)blockIdx.x * blockDim.x + threadIdx.x;
    if (idx >= (size_t)MT * EE) return;
    int r = (int)(idx / EE);
    int c = (int)(idx - (size_t)r * EE);
    float v;
    if (r < M0) v = (c < DD) ? emb1[(size_t)r * DD + c] : td1[(size_t)r * TDD + (c - DD)];
    else {
        int t = r - M0;
        v = (c < DD) ? emb2[(size_t)t * DD + c] : 0.f;
    }
    qin[idx] = v;
}

__global__ void pack_ffnin_kernel(const float* __restrict__ a, const float* __restrict__ emb1,
                                  const float* __restrict__ emb2, float* __restrict__ ffnin)
{
    size_t idx = (size_t)blockIdx.x * blockDim.x + threadIdx.x;
    if (idx >= (size_t)MT * KD_) return;
    int r = (int)(idx / KD_);
    int c = (int)(idx - (size_t)r * KD_);
    float v;
    if (c < EE) v = a[(size_t)r * EE + c];
    else {
        int cc = c - EE;
        v = (r < M0) ? emb1[(size_t)r * DD + cc] : emb2[(size_t)(r - M0) * DD + cc];
    }
    ffnin[idx] = v;
}

// ---------------- mma.sync bf16-split GEMM: kpvp = packed @ Wkv^T + bkv ----------------
// C[m][n] = sum_k (Ahi+Alo)[m][k] * (Bhi+Blo)[n][k], 3-term split, fp32 accum.
// BM=128, BN=128, BK=32, 8 warps (2m x 4n), warp tile 64x32, 2-stage cp.async.
#define TBK 32
#define SSTR 40                 // smem row stride in bf16 elems (80 bytes) -> conflict-free
#define SROW 80                 // bytes per row
#define MAT_BYTES (128 * SROW)  // 10240 per matrix
#define STAGE_BYTES (4 * MAT_BYTES)  // Ah, Al, Bh, Bl
#define MM_SMEM (2 * STAGE_BYTES)    // 81920
#define NIT (K_PAD / TBK)            // 140

__global__ void __launch_bounds__(256)
mma_gemm_kpvp(const __nv_bfloat16* __restrict__ Ahi, const __nv_bfloat16* __restrict__ Alo,
              const __nv_bfloat16* __restrict__ Bhi, const __nv_bfloat16* __restrict__ Blo,
              const float* __restrict__ bias, float* __restrict__ C)
{
    extern __shared__ char smem[];
    const int tid  = threadIdx.x;
    const int wid  = tid >> 5;
    const int lane = tid & 31;
    const int wm = wid >> 2;          // 0..1 : m offset wm*64
    const int wn = wid & 3;           // 0..3 : n offset wn*32
    const int m0 = blockIdx.y * 128;
    const int n0 = blockIdx.x * 128;

    const uint32_t sbase = smem_u32(smem);

    float acc[4][4][4];
#pragma unroll
    for (int mt = 0; mt < 4; mt++)
#pragma unroll
        for (int nt = 0; nt < 4; nt++)
#pragma unroll
            for (int i = 0; i < 4; i++) acc[mt][nt][i] = 0.f;

    // ---- async tile loader: 512 chunks of 16B per matrix, 2 per thread ----
    auto load_stage = [&](int it, int stg) {
        int k0 = it * TBK;
        uint32_t sb = sbase + stg * STAGE_BYTES;
#pragma unroll
        for (int u = tid; u < 512; u += 256) {
            int row = u >> 2, seg = u & 3;
            uint32_t d = sb + row * SROW + seg * 16;
            size_t ga = (size_t)(m0 + row) * K_PAD + k0 + seg * 8;
            CP_ASYNC16(d,                 Ahi + ga, 16);
            CP_ASYNC16(d + MAT_BYTES,     Alo + ga, 16);
            int nrow = n0 + row;
            int ok = (nrow < NKV) ? 16 : 0;
            int crow = nrow < NKV ? nrow : (NKV - 1);
            size_t gb = (size_t)crow * K_PAD + k0 + seg * 8;
            CP_ASYNC16(d + 2 * MAT_BYTES, Bhi + gb, ok);
            CP_ASYNC16(d + 3 * MAT_BYTES, Blo + gb, ok);
        }
        CP_COMMIT();
    };

    load_stage(0, 0);

    for (int it = 0; it < NIT; it++) {
        if (it + 1 < NIT) load_stage(it + 1, (it + 1) & 1);
        if (it + 1 < NIT) { CP_WAIT1(); } else { CP_WAIT0(); }
        __syncthreads();

        const char* st = smem + (it & 1) * STAGE_BYTES;
        const char* pA  = st + (wm * 64) * SROW;
        const char* pB  = st + 2 * MAT_BYTES + (wn * 32) * SROW;

#pragma unroll
        for (int kk = 0; kk < 32; kk += 16) {
            const int rsel = (lane >> 2);         // 0..7
            const int csel = (lane & 3) * 4;      // byte offset within k16 pair group
            // B fragments (hi and lo)
            uint32_t bh[4][2], bl[4][2];
#pragma unroll
            for (int nt = 0; nt < 4; nt++) {
                const char* pb = pB + (nt * 8 + rsel) * SROW + kk * 2 + csel;
                bh[nt][0] = *(const uint32_t*)(pb);
                bh[nt][1] = *(const uint32_t*)(pb + 16);
                bl[nt][0] = *(const uint32_t*)(pb + MAT_BYTES);
                bl[nt][1] = *(const uint32_t*)(pb + MAT_BYTES + 16);
            }
            // A hi fragments
            uint32_t af[4][4];
#pragma unroll
            for (int mt = 0; mt < 4; mt++) {
                const char* pa = pA + (mt * 16 + rsel) * SROW + kk * 2 + csel;
                af[mt][0] = *(const uint32_t*)(pa);
                af[mt][1] = *(const uint32_t*)(pa + 8 * SROW);
                af[mt][2] = *(const uint32_t*)(pa + 16);
                af[mt][3] = *(const uint32_t*)(pa + 8 * SROW + 16);
            }
#pragma unroll
            for (int mt = 0; mt < 4; mt++)
#pragma unroll
                for (int nt = 0; nt < 4; nt++) {
                    mma_bf16(acc[mt][nt], af[mt][0], af[mt][1], af[mt][2], af[mt][3],
                             bh[nt][0], bh[nt][1]);
                    mma_bf16(acc[mt][nt], af[mt][0], af[mt][1], af[mt][2], af[mt][3],
                             bl[nt][0], bl[nt][1]);
                }
            // A lo fragments (reuse regs)
#pragma unroll
            for (int mt = 0; mt < 4; mt++) {
                const char* pa = pA + MAT_BYTES + (mt * 16 + rsel) * SROW + kk * 2 + csel;
                af[mt][0] = *(const uint32_t*)(pa);
                af[mt][1] = *(const uint32_t*)(pa + 8 * SROW);
                af[mt][2] = *(const uint32_t*)(pa + 16);
                af[mt][3] = *(const uint32_t*)(pa + 8 * SROW + 16);
            }
#pragma unroll
            for (int mt = 0; mt < 4; mt++)
#pragma unroll
                for (int nt = 0; nt < 4; nt++)
                    mma_bf16(acc[mt][nt], af[mt][0], af[mt][1], af[mt][2], af[mt][3],
                             bh[nt][0], bh[nt][1]);
        }
        __syncthreads();
    }

    // ---- epilogue: C[m][n] = acc + bias[n] ----
#pragma unroll
    for (int mt = 0; mt < 4; mt++) {
        int mrow = m0 + wm * 64 + mt * 16 + (lane >> 2);
#pragma unroll
        for (int nt = 0; nt < 4; nt++) {
            int n = n0 + wn * 32 + nt * 8 + (lane & 3) * 2;
            if (n < NKV) {
                float b0 = bias[n], b1 = bias[n + 1];
                float* c0 = C + (size_t)mrow * NKV + n;
                c0[0] = acc[mt][nt][0] + b0;
                c0[1] = acc[mt][nt][1] + b1;
                float* c1 = C + (size_t)(mrow + 8) * NKV + n;
                c1[0] = acc[mt][nt][2] + b0;
                c1[1] = acc[mt][nt][3] + b1;
            }
        }
    }
}

// ---------------- generic tiled fp32 GEMM (small GEMMs) ----------------
#define BM 128
#define BN 64
#define BKK 8

template<bool BT>
__global__ void __launch_bounds__(256)
gemm_kernel(const float* __restrict__ A, const float* __restrict__ B, float* __restrict__ C,
            int M, int N, int K, int lda, int ldb, int ldc,
            const float* __restrict__ bias, float alpha, int relu)
{
    __shared__ float As[BKK][BM + 4];
    __shared__ float Bs[BKK][BN + 4];
    int tid = threadIdx.x;
    int m0 = blockIdx.y * BM;
    int n0 = blockIdx.x * BN;
    int tx = tid & 15;
    int ty = tid >> 4;

    float acc[8][4];
#pragma unroll
    for (int i = 0; i < 8; i++)
#pragma unroll
        for (int j = 0; j < 4; j++) acc[i][j] = 0.f;

    int arow = tid >> 1;
    int acol = (tid & 1) * 4;

    for (int k0 = 0; k0 < K; k0 += BKK) {
        float4 av = make_float4(0.f, 0.f, 0.f, 0.f);
        int ka = k0 + acol;
        if (m0 + arow < M && ka < K)
            av = *(const float4*)(A + (size_t)(m0 + arow) * lda + ka);
        As[acol + 0][arow] = av.x;
        As[acol + 1][arow] = av.y;
        As[acol + 2][arow] = av.z;
        As[acol + 3][arow] = av.w;
        if (tid < 128) {
            if (BT) {
                int brow = tid >> 1, bcol = (tid & 1) * 4;
                float4 bv = make_float4(0.f, 0.f, 0.f, 0.f);
                int kb = k0 + bcol;
                if (n0 + brow < N && kb < K)
                    bv = *(const float4*)(B + (size_t)(n0 + brow) * ldb + kb);
                Bs[bcol + 0][brow] = bv.x;
                Bs[bcol + 1][brow] = bv.y;
                Bs[bcol + 2][brow] = bv.z;
                Bs[bcol + 3][brow] = bv.w;
            } else {
                int krow = tid >> 4, nc = (tid & 15) * 4;
                float4 bv = make_float4(0.f, 0.f, 0.f, 0.f);
                if (k0 + krow < K && n0 + nc < N)
                    bv = *(const float4*)(B + (size_t)(k0 + krow) * ldb + n0 + nc);
                *(float4*)&Bs[krow][nc] = bv;
            }
        }
        __syncthreads();
#pragma unroll
        for (int kk = 0; kk < BKK; kk++) {
            float a[8], b[4];
            *(float4*)&a[0] = *(const float4*)&As[kk][ty * 8];
            *(float4*)&a[4] = *(const float4*)&As[kk][ty * 8 + 4];
            *(float4*)&b[0] = *(const float4*)&Bs[kk][tx * 4];
#pragma unroll
            for (int i = 0; i < 8; i++)
#pragma unroll
                for (int j = 0; j < 4; j++)
                    acc[i][j] += a[i] * b[j];
        }
        __syncthreads();
    }
#pragma unroll
    for (int i = 0; i < 8; i++) {
        int m = m0 + ty * 8 + i;
        if (m >= M) continue;
#pragma unroll
        for (int j = 0; j < 4; j++) {
            int nn = n0 + tx * 4 + j;
            if (nn >= N) continue;
            float v = acc[i][j] * alpha;
            if (bias) v += alpha * bias[nn];
            if (relu) v = fmaxf(v, 0.f);
            C[(size_t)m * ldc + nn] = v;
        }
    }
}

// ---------------- prop0 attention ----------------
__global__ void __launch_bounds__(256)
attn0_kernel(const float* __restrict__ qp, const float* __restrict__ kpvp, float* __restrict__ o)
{
    int s = blockIdx.x;
    __shared__ float qs[NN_][EE + 1];
    __shared__ float ks[NN_][EE + 1];
    __shared__ float vs[NN_][EE + 1];
    __shared__ float p[2][NN_][NN_];
    int tid = threadIdx.x;

    for (int idx = tid; idx < NN_ * EE; idx += 256) {
        int n = idx / EE, e = idx - n * EE;
        size_t row = (size_t)(s * NN_ + n);
        qs[n][e] = qp[row * EE + e];
        ks[n][e] = kpvp[row * NKV + e];
        vs[n][e] = kpvp[row * NKV + EE + e];
    }
    __syncthreads();

    if (tid < 200) {
        int h = tid / 100, q = (tid / 10) % 10, k = tid % 10;
        float acc = 0.f;
        const float* qr = &qs[q][h * HD];
        const float* kr = &ks[k][h * HD];
#pragma unroll 8
        for (int d = 0; d < HD; d++) acc += qr[d] * kr[d];
        p[h][q][k] = acc;
    }
    __syncthreads();

    if (tid < 20) {
        int h = tid / 10, q = tid % 10;
        float mx = -1e30f;
#pragma unroll
        for (int k = 0; k < NN_; k++) mx = fmaxf(mx, p[h][q][k]);
        float sum = 0.f;
#pragma unroll
        for (int k = 0; k < NN_; k++) { float e = expf(p[h][q][k] - mx); p[h][q][k] = e; sum += e; }
        float inv = 1.f / sum;
#pragma unroll
        for (int k = 0; k < NN_; k++) p[h][q][k] *= inv;
    }
    __syncthreads();

    for (int idx = tid; idx < NN_ * EE; idx += 256) {
        int q = idx / EE, e = idx - q * EE;
        int h = e / HD;
        float acc = 0.f;
#pragma unroll
        for (int k = 0; k < NN_; k++) acc += p[h][q][k] * vs[k][e];
        o[(size_t)(s * NN_ + q) * EE + e] = acc;
    }
}

// ---------------- row softmax over 2048 cols ----------------
__global__ void __launch_bounds__(256)
softmax2048_kernel(float* __restrict__ Smat)
{
    int row = blockIdx.x;
    float* r = Smat + (size_t)row * SS;
    int tid = threadIdx.x;
    __shared__ float red[256];

    float v[8];
    float mx = -1e30f;
#pragma unroll
    for (int i = 0; i < 8; i++) { v[i] = r[tid + 256 * i]; mx = fmaxf(mx, v[i]); }
    red[tid] = mx; __syncthreads();
    for (int sft = 128; sft > 0; sft >>= 1) {
        if (tid < sft) red[tid] = fmaxf(red[tid], red[tid + sft]);
        __syncthreads();
    }
    mx = red[0]; __syncthreads();

    float sum = 0.f;
#pragma unroll
    for (int i = 0; i < 8; i++) { v[i] = expf(v[i] - mx); sum += v[i]; }
    red[tid] = sum; __syncthreads();
    for (int sft = 128; sft > 0; sft >>= 1) {
        if (tid < sft) red[tid] += red[tid + sft];
        __syncthreads();
    }
    float inv = 1.f / red[0];
#pragma unroll
    for (int i = 0; i < 8; i++) r[tid + 256 * i] = v[i] * inv;
}

// ---------------- host launcher ----------------
static inline void gemm_nt(const float* A, const float* B, float* C, int M, int N, int K,
                           int lda, int ldb, int ldc, const float* bias, float alpha, int relu)
{
    dim3 g((N + BN - 1) / BN, (M + BM - 1) / BM);
    gemm_kernel<true><<<g, 256>>>(A, B, C, M, N, K, lda, ldb, ldc, bias, alpha, relu);
}
static inline void gemm_nn(const float* A, const float* B, float* C, int M, int N, int K,
                           int lda, int ldb, int ldc, const float* bias, float alpha, int relu)
{
    dim3 g((N + BN - 1) / BN, (M + BM - 1) / BM);
    gemm_kernel<false><<<g, 256>>>(A, B, C, M, N, K, lda, ldb, ldc, bias, alpha, relu);
}

extern "C" void kernel_launch(void* const* d_in, const int* in_sizes, int n_in,
                              void* d_out, int out_size)
{
    const float* emb0  = (const float*)d_in[0];
    const float* edge0 = (const float*)d_in[1];
    const float* td0   = (const float*)d_in[2];
    const float* emb1  = (const float*)d_in[3];
    const float* edge1 = (const float*)d_in[4];
    const float* td1   = (const float*)d_in[5];
    const float* emb2  = (const float*)d_in[6];
    const float* Wq = (const float*)d_in[7];
    const float* bq = (const float*)d_in[8];
    const float* Wk = (const float*)d_in[9];
    const float* bk = (const float*)d_in[10];
    const float* Wv = (const float*)d_in[11];
    const float* bv = (const float*)d_in[12];
    const float* Wo = (const float*)d_in[13];
    const float* bo = (const float*)d_in[14];
    const float* W1 = (const float*)d_in[15];
    const float* b1 = (const float*)d_in[16];
    const float* W2 = (const float*)d_in[17];
    const float* b2 = (const float*)d_in[18];
    float* out = (float*)d_out;

    float* base = nullptr;
    cudaGetSymbolAddress((void**)&base, g_scratch);
    __nv_bfloat16 *Ahi, *Alo, *Bhi, *Blo;
    cudaGetSymbolAddress((void**)&Ahi, g_Ahi);
    cudaGetSymbolAddress((void**)&Alo, g_Alo);
    cudaGetSymbolAddress((void**)&Bhi, g_Bhi);
    cudaGetSymbolAddress((void**)&Blo, g_Blo);

    float* qin    = base + OFF_QIN;
    float* kpvp   = base + OFF_KPVP;
    float* qp     = base + OFF_QP;
    float* o      = base + OFF_O;
    float* a      = base + OFF_A;
    float* ffnin  = base + OFF_FFNIN;
    float* h      = base + OFF_H;
    float* sc     = base + OFF_SC;
    float* bkv    = base + OFF_BKV;

    const float qscale = 1.f / sqrtf((float)HD);

    cudaFuncSetAttribute(mma_gemm_kpvp, cudaFuncAttributeMaxDynamicSharedMemorySize, MM_SMEM);

    // --- packs ---
    {
        size_t n = (size_t)NKV * K_PAD;
        pack_wkv_bf16<<<(unsigned)((n + 255) / 256), 256>>>(Wk, Wv, bk, bv, Bhi, Blo, bkv);
    }
    pack_big_bf16<<<dim3((K_PAD + 255) / 256, MT), 256>>>(emb0, edge0, td0, emb1, edge1, td1, Ahi, Alo);
    {
        size_t n = (size_t)MT * EE;
        pack_qin_kernel<<<(unsigned)((n + 255) / 256), 256>>>(emb1, td1, emb2, qin);
    }

    // --- big projection on tensor cores (mma.sync bf16 split, fp32 accumulate) ---
    mma_gemm_kpvp<<<dim3((NKV + 127) / 128, MT / 128), 256, MM_SMEM>>>(Ahi, Alo, Bhi, Blo, bkv, kpvp);

    // --- qp projection (fp32) ---
    gemm_nt(qin, Wq, qp, MT, EE, EE, EE, EE, EE, bq, qscale, 0);

    // --- prop0 attention ---
    attn0_kernel<<<SS, 256>>>(qp, kpvp, o);

    // --- prop1 attention ---
    for (int hh = 0; hh < 2; hh++) {
        gemm_nt(qp + (size_t)M0 * EE + hh * HD,
                kpvp + (size_t)M0 * NKV + hh * HD,
                sc + (size_t)hh * SS * SS,
                SS, SS, HD, EE, NKV, SS, nullptr, 1.f, 0);
    }
    softmax2048_kernel<<<2 * SS, 256>>>(sc);
    for (int hh = 0; hh < 2; hh++) {
        gemm_nn(sc + (size_t)hh * SS * SS,
                kpvp + (size_t)M0 * NKV + EE + hh * HD,
                o + (size_t)M0 * EE + hh * HD,
                SS, HD, SS, SS, NKV, EE, nullptr, 1.f, 0);
    }

    // --- output projection + FFN ---
    gemm_nt(o, Wo, a, MT, EE, EE, EE, EE, EE, bo, 1.f, 0);
    {
        size_t n = (size_t)MT * KD_;
        pack_ffnin_kernel<<<(unsigned)((n + 255) / 256), 256>>>(a, emb1, emb2, ffnin);
    }
    gemm_nt(ffnin, W1, h, MT, DD, KD_, KD_, KD_, DD, b1, 1.f, 1);
    gemm_nt(h, W2, out, MT, DD, DD, DD, DD, DD, b2, 1.f, 0);

    // --- passthrough outputs ---
    const size_t r_elems  = (size_t)MT * DD;
    const size_t e_elems  = (size_t)M0 * EDGE;
    const size_t t_elems  = (size_t)M0 * TDD;
    cudaMemcpyAsync(out + r_elems, edge1, e_elems * sizeof(float), cudaMemcpyDeviceToDevice);
    cudaMemcpyAsync(out + r_elems + e_elems, td1, t_elems * sizeof(float), cudaMemcpyDeviceToDevice);
}